// round 16
// baseline (speedup 1.0000x reference)
#include <cuda_runtime.h>
#include <cuda_bf16.h>
#include <mma.h>
#include <math.h>
#include <stdint.h>

using namespace nvcuda;

#define B_  2
#define T_  1024
#define E_  1024
#define H_  16
#define HD_ 64
#define FF_ 4096
#define L_  8
#define V_  50257
#define M_  (B_*T_)   // 2048

// ===================== scratch (device globals) =====================
__device__ float g_x   [M_*E_];
__device__ float g_x0  [M_*E_];
__device__ float g_qkv [M_*3*E_];
__device__ float g_gate[M_*H_];
__device__ float g_cosT[T_*HD_];
__device__ float g_sinT[T_*HD_];

// split bf16 q/k/v: [B*H][T][hi(64)|lo(64)]
__device__ __nv_bfloat16 g_q2[(size_t)B_*H_*T_*128];
__device__ __nv_bfloat16 g_k2[(size_t)B_*H_*T_*128];
__device__ __nv_bfloat16 g_v2[(size_t)B_*H_*T_*128];

// bf16 [hi|lo] 2K-layout buffers
__device__ __nv_bfloat16 g_wqkv2[(size_t)L_*3*E_*2*E_];
__device__ __nv_bfloat16 g_wout2[(size_t)L_*E_*2*E_];
__device__ __nv_bfloat16 g_wgu2 [(size_t)L_*2*FF_*2*E_];   // rows interleaved: 2f=wg_f, 2f+1=wu_f
__device__ __nv_bfloat16 g_wd2  [(size_t)L_*E_*2*FF_];
__device__ __nv_bfloat16 g_tok2 [(size_t)V_*2*E_];
__device__ __nv_bfloat16 g_a2s  [(size_t)M_*2*E_];
__device__ __nv_bfloat16 g_a2b  [(size_t)M_*2*FF_];

__device__ __forceinline__ void split_store(__nv_bfloat16* row, int d, float v) {
    __nv_bfloat16 hh = __float2bfloat16(v);
    row[d]      = hh;
    row[64 + d] = __float2bfloat16(v - __bfloat162float(hh));
}

// ===================== vectorized hi/lo split conversion =====================
__global__ void cvt2(const float* __restrict__ src, __nv_bfloat16* __restrict__ dst,
                     int K, long long total8, int RPL, long long ostride, int ooff,
                     int rmul) {
    long long i8 = (long long)blockIdx.x * 256 + threadIdx.x;
    if (i8 >= total8) return;
    long long i = i8 * 8;
    long long r = i / K;
    int k = (int)(i - r * (long long)K);
    long long layer = r / RPL;
    long long dr = layer * ostride + ooff + (long long)rmul * (r - layer * RPL);

    const float4* sp = (const float4*)(src + r * (long long)K + k);
    float4 f0 = sp[0], f1 = sp[1];
    float fv[8] = {f0.x, f0.y, f0.z, f0.w, f1.x, f1.y, f1.z, f1.w};

    union { __nv_bfloat162 b2[4]; uint4 u; } hi, lo;
#pragma unroll
    for (int j = 0; j < 4; j++) {
        __nv_bfloat16 h0 = __float2bfloat16(fv[2*j]);
        __nv_bfloat16 h1 = __float2bfloat16(fv[2*j+1]);
        hi.b2[j] = __nv_bfloat162(h0, h1);
        lo.b2[j] = __floats2bfloat162_rn(fv[2*j]   - __bfloat162float(h0),
                                         fv[2*j+1] - __bfloat162float(h1));
    }
    __nv_bfloat16* dbase = dst + dr * (long long)(2 * K);
    *((uint4*)(dbase + k))     = hi.u;
    *((uint4*)(dbase + K + k)) = lo.u;
}

// ===================== cp.async helpers =====================
__device__ __forceinline__ void cp_async16(uint32_t dst, const void* src, bool pred) {
    int sz = pred ? 16 : 0;
    asm volatile("cp.async.cg.shared.global [%0], [%1], 16, %2;"
                 :: "r"(dst), "l"(src), "r"(sz) : "memory");
}
#define CP_COMMIT() asm volatile("cp.async.commit_group;" ::: "memory")
#define CP_WAIT(n)  asm volatile("cp.async.wait_group %0;" :: "n"(n) : "memory")

enum { EP_NONE = 0, EP_ADD = 1, EP_TANH = 2, EP_SWIGLU = 3 };

// ========== unified GEMM: BM64/BN128, BK=64 hi/lo stages, NST=2 =============
#define PAD2 72                          // 64 + 8 bf16; pitch 144B

__device__ __forceinline__ void load_hl64(uint32_t sbase,
                                          const __nv_bfloat16* __restrict__ A,
                                          const __nv_bfloat16* __restrict__ Bm,
                                          int m0, int n0, int N, int K,
                                          int kp, int tid) {
    const int ld2 = 2 * K;
#pragma unroll
    for (int part = 0; part < 2; part++) {          // A: hi, lo (64 rows x 8 chunks)
        const __nv_bfloat16* src = A + part * K + kp * 64;
#pragma unroll
        for (int it = 0; it < 2; it++) {
            int id = it * 256 + tid;
            int r = id >> 3, c = id & 7;
            uint32_t dst = sbase + (uint32_t)((part * 64 + r) * PAD2 + c * 8) * 2;
            cp_async16(dst, src + (size_t)(m0 + r) * ld2 + c * 8, true);
        }
    }
#pragma unroll
    for (int part = 0; part < 2; part++) {          // B: hi, lo (128 rows x 8 chunks)
        const __nv_bfloat16* src = Bm + part * K + kp * 64;
#pragma unroll
        for (int it = 0; it < 4; it++) {
            int id = it * 256 + tid;
            int r = id >> 3, c = id & 7;
            bool ok = (n0 + r) < N;
            int gn = ok ? (n0 + r) : 0;
            uint32_t dst = sbase +
                (uint32_t)((128 + part * 128 + r) * PAD2 + c * 8) * 2;
            cp_async16(dst, src + (size_t)gn * ld2 + c * 8, ok);
        }
    }
}

template <int EPI>
__global__ __launch_bounds__(256, 2)
void gemm_hl64(const __nv_bfloat16* __restrict__ A,
               const __nv_bfloat16* __restrict__ Bm,
               float* __restrict__ C,
               int M, int N, int K) {
    constexpr int NJ      = 2;                  // 2 warps M, 4 warps N
    constexpr int STAGE_E = (2 * 64 + 2 * 128) * PAD2;   // 384*72
    constexpr int STAGE_B = STAGE_E * 2;                 // 55296 B

    extern __shared__ __nv_bfloat16 smem[];
    const uint32_t sm0 = (uint32_t)__cvta_generic_to_shared(smem);
    const int tid  = threadIdx.x;
    const int warp = tid >> 5, lane = tid & 31;
    const int wm = warp % 2;
    const int wn = warp / 2;
    const int m0 = blockIdx.x * 64;             // M fastest
    const int n0 = blockIdx.y * 128;
    const int NK = K / 64;

    wmma::fragment<wmma::accumulator, 16, 16, 16, float> acc[2][NJ];
#pragma unroll
    for (int i = 0; i < 2; i++)
#pragma unroll
        for (int j = 0; j < NJ; j++) wmma::fill_fragment(acc[i][j], 0.f);

    load_hl64(sm0, A, Bm, m0, n0, N, K, 0, tid);
    CP_COMMIT();

    for (int kt = 0; kt < NK; kt++) {
        CP_WAIT(0);
        __syncthreads();
        int cn = kt + 1;
        if (cn < NK) {
            load_hl64(sm0 + (cn & 1) * STAGE_B, A, Bm, m0, n0, N, K, cn, tid);
            CP_COMMIT();
        }

        const __nv_bfloat16* st = smem + (size_t)(kt & 1) * STAGE_E;
        const __nv_bfloat16* aH = st;
        const __nv_bfloat16* aL = st + 64 * PAD2;
        const __nv_bfloat16* bH = st + 128 * PAD2;
        const __nv_bfloat16* bL = bH + 128 * PAD2;
#pragma unroll
        for (int ks = 0; ks < 4; ks++) {
            wmma::fragment<wmma::matrix_a, 16, 16, 16, __nv_bfloat16, wmma::row_major> afH[2], afL[2];
            wmma::fragment<wmma::matrix_b, 16, 16, 16, __nv_bfloat16, wmma::col_major> bfH[NJ], bfL[NJ];
#pragma unroll
            for (int i = 0; i < 2; i++) {
                wmma::load_matrix_sync(afH[i], aH + (wm * 32 + i * 16) * PAD2 + ks * 16, PAD2);
                wmma::load_matrix_sync(afL[i], aL + (wm * 32 + i * 16) * PAD2 + ks * 16, PAD2);
            }
#pragma unroll
            for (int j = 0; j < NJ; j++) {
                wmma::load_matrix_sync(bfH[j], bH + (wn * 32 + j * 16) * PAD2 + ks * 16, PAD2);
                wmma::load_matrix_sync(bfL[j], bL + (wn * 32 + j * 16) * PAD2 + ks * 16, PAD2);
            }
#pragma unroll
            for (int i = 0; i < 2; i++)
#pragma unroll
                for (int j = 0; j < NJ; j++)
                    wmma::mma_sync(acc[i][j], afH[i], bfH[j], acc[i][j]);
#pragma unroll
            for (int i = 0; i < 2; i++)
#pragma unroll
                for (int j = 0; j < NJ; j++)
                    wmma::mma_sync(acc[i][j], afH[i], bfL[j], acc[i][j]);
#pragma unroll
            for (int i = 0; i < 2; i++)
#pragma unroll
                for (int j = 0; j < NJ; j++)
                    wmma::mma_sync(acc[i][j], afL[i], bfH[j], acc[i][j]);
        }
    }

    if (EPI == EP_TANH || EPI == EP_SWIGLU) {
        __syncthreads();
        float* scr = reinterpret_cast<float*>(smem) + warp * 256;
        __nv_bfloat16* Cb = reinterpret_cast<__nv_bfloat16*>(C);
#pragma unroll
        for (int i = 0; i < 2; i++) {
#pragma unroll
            for (int j = 0; j < NJ; j++) {
                wmma::store_matrix_sync(scr, acc[i][j], 16, wmma::mem_row_major);
                __syncwarp();
                int r0 = m0 + wm * 32 + i * 16;
                int c0 = n0 + wn * 32 + j * 16;
                if (EPI == EP_TANH) {
#pragma unroll
                    for (int e = lane; e < 256; e += 32) {
                        int rr = e >> 4, cc = e & 15;
                        int gc = c0 + cc;
                        if (gc < N) {
                            size_t off = (size_t)(r0 + rr) * N + gc;
                            C[off] = 30.f * tanhf(scr[e] * (1.f / 30.f));
                        }
                    }
                } else {  // EP_SWIGLU: cols interleaved (2f=g, 2f+1=u); write split bf16
                    int f0 = c0 >> 1;
#pragma unroll
                    for (int e = lane; e < 128; e += 32) {
                        int rr = e >> 3, pp = e & 7;
                        float g = scr[rr * 16 + 2 * pp];
                        float u = scr[rr * 16 + 2 * pp + 1];
                        float v = (g / (1.f + expf(-g))) * u;
                        __nv_bfloat16 hh = __float2bfloat16(v);
                        __nv_bfloat16 ll = __float2bfloat16(v - __bfloat162float(hh));
                        size_t base = (size_t)(r0 + rr) * N;   // N bf16/row = [hi|lo]
                        Cb[base + f0 + pp]            = hh;
                        Cb[base + (N >> 1) + f0 + pp] = ll;
                    }
                }
                __syncwarp();
            }
        }
    } else {
        // direct fragment epilogue (N % 128 == 0 at these call sites)
#pragma unroll
        for (int i = 0; i < 2; i++) {
#pragma unroll
            for (int j = 0; j < NJ; j++) {
                int r0 = m0 + wm * 32 + i * 16;
                int c0 = n0 + wn * 32 + j * 16;
                float* cp = C + (size_t)r0 * N + c0;
                if (EPI == EP_ADD) {
                    wmma::fragment<wmma::accumulator, 16, 16, 16, float> cf;
                    wmma::load_matrix_sync(cf, cp, N, wmma::mem_row_major);
#pragma unroll
                    for (int e = 0; e < cf.num_elements; e++)
                        acc[i][j].x[e] += cf.x[e];
                }
                wmma::store_matrix_sync(cp, acc[i][j], N, wmma::mem_row_major);
            }
        }
    }
}

// ===================== elementwise kernels =====================
__global__ void embed_kernel(const int* __restrict__ idx, const float* __restrict__ tok) {
    int i = blockIdx.x * 256 + threadIdx.x;
    int bt = i >> 10;
    int e  = i & (E_ - 1);
    float v = tok[(size_t)idx[bt] * E_ + e];
    g_x[i]  = v;
    g_x0[i] = v;
}

__global__ void rope_table_kernel() {
    int i = blockIdx.x * 256 + threadIdx.x;
    int t = i >> 6, d = i & 63;
    float ang = (float)t * powf(10000.f, -(float)(d & 31) * (1.f / 32.f));
    float s, c;
    sincosf(ang, &s, &c);
    g_cosT[i] = c;
    g_sinT[i] = s;
}

// rmsnorm -> split bf16 activation; optional fused ve-gate (needs h[0:32])
__global__ void rmsnorm_split(const float* __restrict__ x, const float* __restrict__ w,
                              __nv_bfloat16* __restrict__ a2,
                              const float* __restrict__ vgw) {
    __shared__ float red[8];
    __shared__ float h32[32];
    int row = blockIdx.x;
    int tid = threadIdx.x;
    const float4 xv = ((const float4*)(x + (size_t)row * E_))[tid];
    float s = xv.x*xv.x + xv.y*xv.y + xv.z*xv.z + xv.w*xv.w;
#pragma unroll
    for (int o = 16; o; o >>= 1) s += __shfl_xor_sync(0xFFFFFFFFu, s, o);
    if ((tid & 31) == 0) red[tid >> 5] = s;
    __syncthreads();
    if (tid == 0) {
        float t = 0.f;
#pragma unroll
        for (int i = 0; i < 8; i++) t += red[i];
        red[0] = rsqrtf(t * (1.f / E_) + 1e-6f);
    }
    __syncthreads();
    float norm = red[0];
    const float4 wv = ((const float4*)w)[tid];
    float v[4] = {xv.x*norm*wv.x, xv.y*norm*wv.y, xv.z*norm*wv.z, xv.w*norm*wv.w};
    if (vgw && tid < 8) {
        h32[tid * 4]     = v[0];
        h32[tid * 4 + 1] = v[1];
        h32[tid * 4 + 2] = v[2];
        h32[tid * 4 + 3] = v[3];
    }
    union { __nv_bfloat162 b2[2]; uint2 u; } hi, lo;
#pragma unroll
    for (int j = 0; j < 2; j++) {
        __nv_bfloat16 h0 = __float2bfloat16(v[2*j]);
        __nv_bfloat16 h1 = __float2bfloat16(v[2*j+1]);
        hi.b2[j] = __nv_bfloat162(h0, h1);
        lo.b2[j] = __floats2bfloat162_rn(v[2*j] - __bfloat162float(h0),
                                         v[2*j+1] - __bfloat162float(h1));
    }
    __nv_bfloat16* dbase = a2 + (size_t)row * 2 * E_ + tid * 4;
    *((uint2*)dbase)        = hi.u;
    *((uint2*)(dbase + E_)) = lo.u;
    if (vgw) {
        __syncthreads();
        if (tid < H_) {
            const float* wr = vgw + tid * 32;
            float g = 0.f;
#pragma unroll
            for (int c = 0; c < 32; c++) g = fmaf(h32[c], wr[c], g);
            g_gate[row * H_ + tid] = 2.f / (1.f + expf(-g));
        }
    }
}

// rope + head split + gate; writes split bf16 q/k/v [bh][t][hi|lo]
__global__ void rope_split_kernel(const float* __restrict__ qkv, int has_gate) {
    int bt = blockIdx.x;
    int b = bt / T_, t = bt % T_;
    const float* src = qkv + (size_t)bt * 3 * E_;
    const float* ct = g_cosT + t * HD_;
    const float* st = g_sinT + t * HD_;
#pragma unroll
    for (int which = 0; which < 2; ++which) {
        const float* sp = src + which * E_;
        __nv_bfloat16* dst = (which == 0) ? g_q2 : g_k2;
        for (int item = threadIdx.x; item < H_ * 32; item += blockDim.x) {
            int h = item >> 5, p = item & 31;
            int d0 = 2 * p, d1 = 2 * p + 1;
            float c0 = ct[d0], s0 = st[d0];
            float c1 = ct[d1], s1 = st[d1];
            float x0v = sp[h * HD_ + d0];
            float x1v = sp[h * HD_ + d1];
            float o0 = x0v * c0 - x1v * s0;
            float o1 = x1v * c1 + x0v * s1;
            __nv_bfloat16* row = dst + ((size_t)(b * H_ + h) * T_ + t) * 128;
            split_store(row, d0, o0);
            split_store(row, d1, o1);
        }
    }
    for (int item = threadIdx.x; item < E_; item += blockDim.x) {
        int h = item >> 6, d = item & 63;
        float vv = src[2 * E_ + item];
        if (has_gate)
            vv += g_gate[bt * H_ + h] * g_x0[(size_t)bt * E_ + item];
        __nv_bfloat16* row = g_v2 + ((size_t)(b * H_ + h) * T_ + t) * 128;
        split_store(row, d, vv);
    }
}

// ===================== tensor-core causal attention =====================
#define ATP 72      // bf16 pitch
#define ATF 68      // fp32 pitch
#define AT_SMEM (8 * 64 * ATP * 2 + 2 * 64 * ATF * 4 + 3 * 64 * 4)   // 109312

__device__ __forceinline__ void at_load_tile(uint32_t dstH, uint32_t dstL,
                                             const __nv_bfloat16* src, int tid) {
#pragma unroll
    for (int it = 0; it < 4; it++) {
        int id = it * 128 + tid;
        int r = id >> 3, c = id & 7;
        cp_async16(dstH + (uint32_t)(r * ATP + c * 8) * 2, src + r * 128 + c * 8, true);
        cp_async16(dstL + (uint32_t)(r * ATP + c * 8) * 2, src + r * 128 + 64 + c * 8, true);
    }
}

__global__ __launch_bounds__(128, 2) void attn_tc() {
    extern __shared__ char smc[];
    __nv_bfloat16* QH = (__nv_bfloat16*)smc;
    __nv_bfloat16* QL = QH + 64 * ATP;
    __nv_bfloat16* KH = QL + 64 * ATP;
    __nv_bfloat16* KL = KH + 64 * ATP;
    __nv_bfloat16* VH = KL + 64 * ATP;
    __nv_bfloat16* VL = VH + 64 * ATP;
    __nv_bfloat16* PH = VL + 64 * ATP;
    __nv_bfloat16* PL = PH + 64 * ATP;
    float* S  = (float*)(PL + 64 * ATP);
    float* O  = S + 64 * ATF;
    float* Ms = O + 64 * ATF;
    float* Lv = Ms + 64;
    float* CR = Lv + 64;

    const int tid  = threadIdx.x;
    const int warp = tid >> 5;
    const int bh = blockIdx.y;
    const int qt = gridDim.x - 1 - blockIdx.x;

    const uint32_t qh_a = (uint32_t)__cvta_generic_to_shared(QH);
    const uint32_t ql_a = (uint32_t)__cvta_generic_to_shared(QL);
    const uint32_t kh_a = (uint32_t)__cvta_generic_to_shared(KH);
    const uint32_t kl_a = (uint32_t)__cvta_generic_to_shared(KL);
    const uint32_t vh_a = (uint32_t)__cvta_generic_to_shared(VH);
    const uint32_t vl_a = (uint32_t)__cvta_generic_to_shared(VL);

    at_load_tile(qh_a, ql_a, g_q2 + ((size_t)bh * T_ + qt * 64) * 128, tid);
    CP_COMMIT();

    for (int e = tid; e < 4096; e += 128)
        O[(e >> 6) * ATF + (e & 63)] = 0.f;
    if (tid < 64) { Ms[tid] = -1e30f; Lv[tid] = 0.f; }
    CP_WAIT(0);
    __syncthreads();

    for (int kt = 0; kt <= qt; kt++) {
        at_load_tile(kh_a, kl_a, g_k2 + ((size_t)bh * T_ + kt * 64) * 128, tid);
        at_load_tile(vh_a, vl_a, g_v2 + ((size_t)bh * T_ + kt * 64) * 128, tid);
        CP_COMMIT();
        CP_WAIT(0);
        __syncthreads();

        // S = Q K^T
        {
            wmma::fragment<wmma::accumulator, 16, 16, 16, float> sacc[4];
#pragma unroll
            for (int j = 0; j < 4; j++) wmma::fill_fragment(sacc[j], 0.f);
#pragma unroll
            for (int ks = 0; ks < 4; ks++) {
                wmma::fragment<wmma::matrix_a, 16, 16, 16, __nv_bfloat16, wmma::row_major> aH, aL;
                wmma::fragment<wmma::matrix_b, 16, 16, 16, __nv_bfloat16, wmma::col_major> bH[4], bL[4];
                wmma::load_matrix_sync(aH, QH + (warp * 16) * ATP + ks * 16, ATP);
                wmma::load_matrix_sync(aL, QL + (warp * 16) * ATP + ks * 16, ATP);
#pragma unroll
                for (int j = 0; j < 4; j++) {
                    wmma::load_matrix_sync(bH[j], KH + (j * 16) * ATP + ks * 16, ATP);
                    wmma::load_matrix_sync(bL[j], KL + (j * 16) * ATP + ks * 16, ATP);
                }
#pragma unroll
                for (int j = 0; j < 4; j++) wmma::mma_sync(sacc[j], aH, bH[j], sacc[j]);
#pragma unroll
                for (int j = 0; j < 4; j++) wmma::mma_sync(sacc[j], aH, bL[j], sacc[j]);
#pragma unroll
                for (int j = 0; j < 4; j++) wmma::mma_sync(sacc[j], aL, bH[j], sacc[j]);
            }
#pragma unroll
            for (int j = 0; j < 4; j++)
                wmma::store_matrix_sync(S + (warp * 16) * ATF + j * 16, sacc[j], ATF,
                                        wmma::mem_row_major);
        }
        __syncthreads();

        // online softmax (2 threads per row)
        {
            int r = tid >> 1, hf = tid & 1;
            int q = qt * 64 + r;
            int jmax = q - kt * 64 + 1;
            if (jmax > 64) jmax = 64;
            const float* srow = S + r * ATF + hf * 32;
            int base = hf * 32;
            float mo = Ms[r], mx = mo;
#pragma unroll
            for (int j = 0; j < 32; j++) {
                if (base + j < jmax) mx = fmaxf(mx, srow[j] * 0.125f);
            }
            mx = fmaxf(mx, __shfl_xor_sync(0xFFFFFFFFu, mx, 1));
            float corr = __expf(mo - mx);
            float lsum = 0.f;
#pragma unroll
            for (int j = 0; j < 32; j++) {
                int gj = base + j;
                float p = (gj < jmax) ? __expf(srow[j] * 0.125f - mx) : 0.f;
                lsum += p;
                __nv_bfloat16 ph = __float2bfloat16(p);
                PH[r * ATP + gj] = ph;
                PL[r * ATP + gj] = __float2bfloat16(p - __bfloat162float(ph));
            }
            lsum += __shfl_xor_sync(0xFFFFFFFFu, lsum, 1);
            if (hf == 0) {
                Lv[r] = Lv[r] * corr + lsum;
                Ms[r] = mx;
                CR[r] = corr;
            }
        }
        __syncthreads();

        // PV into S temp
        {
            wmma::fragment<wmma::accumulator, 16, 16, 16, float> oacc[4];
#pragma unroll
            for (int j = 0; j < 4; j++) wmma::fill_fragment(oacc[j], 0.f);
#pragma unroll
            for (int ks = 0; ks < 4; ks++) {
                wmma::fragment<wmma::matrix_a, 16, 16, 16, __nv_bfloat16, wmma::row_major> aH, aL;
                wmma::fragment<wmma::matrix_b, 16, 16, 16, __nv_bfloat16, wmma::row_major> bH[4], bL[4];
                wmma::load_matrix_sync(aH, PH + (warp * 16) * ATP + ks * 16, ATP);
                wmma::load_matrix_sync(aL, PL + (warp * 16) * ATP + ks * 16, ATP);
#pragma unroll
                for (int j = 0; j < 4; j++) {
                    wmma::load_matrix_sync(bH[j], VH + (ks * 16) * ATP + j * 16, ATP);
                    wmma::load_matrix_sync(bL[j], VL + (ks * 16) * ATP + j * 16, ATP);
                }
#pragma unroll
                for (int j = 0; j < 4; j++) wmma::mma_sync(oacc[j], aH, bH[j], oacc[j]);
#pragma unroll
                for (int j = 0; j < 4; j++) wmma::mma_sync(oacc[j], aH, bL[j], oacc[j]);
#pragma unroll
                for (int j = 0; j < 4; j++) wmma::mma_sync(oacc[j], aL, bH[j], oacc[j]);
            }
            __syncthreads();
#pragma unroll
            for (int j = 0; j < 4; j++)
                wmma::store_matrix_sync(S + (warp * 16) * ATF + j * 16, oacc[j], ATF,
                                        wmma::mem_row_major);
        }
        __syncthreads();

        for (int e = tid; e < 4096; e += 128) {
            int r = e >> 6, c = e & 63;
            O[r * ATF + c] = O[r * ATF + c] * CR[r] + S[r * ATF + c];
        }
        __syncthreads();
    }

    if (tid < 64) CR[tid] = 1.f / Lv[tid];
    __syncthreads();
    int b = bh / H_, h = bh % H_;
    for (int e = tid; e < 4096; e += 128) {
        int r = e >> 6, c = e & 63;
        int q = qt * 64 + r;
        float v = O[r * ATF + c] * CR[r];
        __nv_bfloat16 hh = __float2bfloat16(v);
        __nv_bfloat16 ll = __float2bfloat16(v - __bfloat162float(hh));
        size_t base = (size_t)(b * T_ + q) * 2 * E_ + h * 64 + c;
        g_a2s[base]      = hh;
        g_a2s[base + E_] = ll;
    }
}

// ===================== host-side launchers =====================
template <int EPI>
static void run_gemm64(const __nv_bfloat16* A2, const __nv_bfloat16* B2, float* C,
                       int M, int N, int K) {
    constexpr size_t SMB = 2 * (size_t)(2 * 64 + 2 * 128) * PAD2 * 2; // 110592
    dim3 grid(M / 64, (N + 127) / 128);
    gemm_hl64<EPI><<<grid, 256, SMB>>>(A2, B2, C, M, N, K);
}

static void run_cvt2(const float* src, __nv_bfloat16* dst, int K, long long rows,
                     int RPL, long long ostride, int ooff, int rmul = 1) {
    long long total8 = rows * K / 8;
    unsigned blocks = (unsigned)((total8 + 255) / 256);
    cvt2<<<blocks, 256>>>(src, dst, K, total8, RPL, ostride, ooff, rmul);
}

// ===================== launch =====================
extern "C" void kernel_launch(void* const* d_in, const int* in_sizes, int n_in,
                              void* d_out, int out_size) {
    const int*   idx  = (const int*)  d_in[0];
    const float* tok  = (const float*)d_in[1];
    const float* ln1  = (const float*)d_in[2];
    const float* qkvw = (const float*)d_in[3];
    const float* outw = (const float*)d_in[4];
    const float* vgw  = (const float*)d_in[5];
    const float* ln2  = (const float*)d_in[6];
    const float* wgw  = (const float*)d_in[7];
    const float* wuw  = (const float*)d_in[8];
    const float* wdw  = (const float*)d_in[9];
    const float* lnf  = (const float*)d_in[10];
    float* out = (float*)d_out;

    constexpr int SMB64 = 2 * (2 * 64 + 2 * 128) * PAD2 * 2;  // 110592
    cudaFuncSetAttribute((void*)gemm_hl64<EP_NONE>,
                         cudaFuncAttributeMaxDynamicSharedMemorySize, SMB64);
    cudaFuncSetAttribute((void*)gemm_hl64<EP_ADD>,
                         cudaFuncAttributeMaxDynamicSharedMemorySize, SMB64);
    cudaFuncSetAttribute((void*)gemm_hl64<EP_SWIGLU>,
                         cudaFuncAttributeMaxDynamicSharedMemorySize, SMB64);
    cudaFuncSetAttribute((void*)gemm_hl64<EP_TANH>,
                         cudaFuncAttributeMaxDynamicSharedMemorySize, SMB64);
    cudaFuncSetAttribute((void*)attn_tc,
                         cudaFuncAttributeMaxDynamicSharedMemorySize, AT_SMEM);

    float *x, *qkv;
    cudaGetSymbolAddress((void**)&x,   g_x);
    cudaGetSymbolAddress((void**)&qkv, g_qkv);

    __nv_bfloat16 *wqkv2, *wout2, *wgu2, *wd2, *tok2, *a2s, *a2b;
    cudaGetSymbolAddress((void**)&wqkv2, g_wqkv2);
    cudaGetSymbolAddress((void**)&wout2, g_wout2);
    cudaGetSymbolAddress((void**)&wgu2,  g_wgu2);
    cudaGetSymbolAddress((void**)&wd2,   g_wd2);
    cudaGetSymbolAddress((void**)&tok2,  g_tok2);
    cudaGetSymbolAddress((void**)&a2s,   g_a2s);
    cudaGetSymbolAddress((void**)&a2b,   g_a2b);

    // ---- one-time prep ----
    rope_table_kernel<<<(T_ * HD_) / 256, 256>>>();
    run_cvt2(qkvw, wqkv2, E_,  (long long)L_ * 3 * E_, 3 * E_,  3 * E_,  0);
    run_cvt2(outw, wout2, E_,  (long long)L_ * E_,     E_,      E_,      0);
    run_cvt2(wgw,  wgu2,  E_,  (long long)L_ * FF_,    FF_,     2 * FF_, 0, 2);
    run_cvt2(wuw,  wgu2,  E_,  (long long)L_ * FF_,    FF_,     2 * FF_, 1, 2);
    run_cvt2(wdw,  wd2,   FF_, (long long)L_ * E_,     E_,      E_,      0);
    run_cvt2(tok,  tok2,  E_,  (long long)V_,          V_,      V_,      0);

    embed_kernel<<<(M_ * E_) / 256, 256>>>(idx, tok);

    for (int i = 0; i < L_; i++) {
        rmsnorm_split<<<M_, 256>>>(x, ln1 + i * E_, a2s,
                                   (i & 1) ? (vgw + (size_t)i * H_ * 32) : nullptr);
        run_gemm64<EP_NONE>(a2s, wqkv2 + (size_t)i * 3 * E_ * 2 * E_,
                            qkv, M_, 3 * E_, E_);
        rope_split_kernel<<<M_, 256>>>(qkv, i & 1);
        attn_tc<<<dim3(T_ / 64, B_ * H_), 128, AT_SMEM>>>();   // writes split into a2s
        run_gemm64<EP_ADD>(a2s, wout2 + (size_t)i * E_ * 2 * E_, x, M_, E_, E_);

        rmsnorm_split<<<M_, 256>>>(x, ln2 + i * E_, a2s, nullptr);
        run_gemm64<EP_SWIGLU>(a2s, wgu2 + (size_t)i * 2 * FF_ * 2 * E_,
                              (float*)a2b, M_, 2 * FF_, E_);
        run_gemm64<EP_ADD>(a2b, wd2 + (size_t)i * E_ * 2 * FF_, x, M_, E_, FF_);
    }

    rmsnorm_split<<<M_, 256>>>(x, lnf, a2s, nullptr);
    run_gemm64<EP_TANH>(a2s, tok2, out, M_, V_, E_);
}

// round 17
// speedup vs baseline: 1.0473x; 1.0473x over previous
#include <cuda_runtime.h>
#include <cuda_bf16.h>
#include <mma.h>
#include <math.h>
#include <stdint.h>

using namespace nvcuda;

#define B_  2
#define T_  1024
#define E_  1024
#define H_  16
#define HD_ 64
#define FF_ 4096
#define L_  8
#define V_  50257
#define M_  (B_*T_)   // 2048

// ===================== scratch (device globals) =====================
__device__ float g_x   [M_*E_];
__device__ float g_x0  [M_*E_];
__device__ float g_qkv [M_*3*E_];
__device__ float g_gate[M_*H_];
__device__ float g_cosT[T_*HD_];
__device__ float g_sinT[T_*HD_];

// split bf16 q/k/v: [B*H][T][hi(64)|lo(64)]
__device__ __nv_bfloat16 g_q2[(size_t)B_*H_*T_*128];
__device__ __nv_bfloat16 g_k2[(size_t)B_*H_*T_*128];
__device__ __nv_bfloat16 g_v2[(size_t)B_*H_*T_*128];

// bf16 [hi|lo] 2K-layout buffers
__device__ __nv_bfloat16 g_wqkv2[(size_t)L_*3*E_*2*E_];
__device__ __nv_bfloat16 g_wout2[(size_t)L_*E_*2*E_];
__device__ __nv_bfloat16 g_wgu2 [(size_t)L_*2*FF_*2*E_];   // rows interleaved: 2f=wg_f, 2f+1=wu_f
__device__ __nv_bfloat16 g_wd2  [(size_t)L_*E_*2*FF_];
__device__ __nv_bfloat16 g_tok2 [(size_t)V_*2*E_];
__device__ __nv_bfloat16 g_a2s  [(size_t)M_*2*E_];
__device__ __nv_bfloat16 g_a2b  [(size_t)M_*2*FF_];

__device__ __forceinline__ void split_store(__nv_bfloat16* row, int d, float v) {
    __nv_bfloat16 hh = __float2bfloat16(v);
    row[d]      = hh;
    row[64 + d] = __float2bfloat16(v - __bfloat162float(hh));
}

// ===================== vectorized hi/lo split conversion =====================
__global__ void cvt2(const float* __restrict__ src, __nv_bfloat16* __restrict__ dst,
                     int K, long long total8, int RPL, long long ostride, int ooff,
                     int rmul) {
    long long i8 = (long long)blockIdx.x * 256 + threadIdx.x;
    if (i8 >= total8) return;
    long long i = i8 * 8;
    long long r = i / K;
    int k = (int)(i - r * (long long)K);
    long long layer = r / RPL;
    long long dr = layer * ostride + ooff + (long long)rmul * (r - layer * RPL);

    const float4* sp = (const float4*)(src + r * (long long)K + k);
    float4 f0 = sp[0], f1 = sp[1];
    float fv[8] = {f0.x, f0.y, f0.z, f0.w, f1.x, f1.y, f1.z, f1.w};

    union { __nv_bfloat162 b2[4]; uint4 u; } hi, lo;
#pragma unroll
    for (int j = 0; j < 4; j++) {
        __nv_bfloat16 h0 = __float2bfloat16(fv[2*j]);
        __nv_bfloat16 h1 = __float2bfloat16(fv[2*j+1]);
        hi.b2[j] = __nv_bfloat162(h0, h1);
        lo.b2[j] = __floats2bfloat162_rn(fv[2*j]   - __bfloat162float(h0),
                                         fv[2*j+1] - __bfloat162float(h1));
    }
    __nv_bfloat16* dbase = dst + dr * (long long)(2 * K);
    *((uint4*)(dbase + k))     = hi.u;
    *((uint4*)(dbase + K + k)) = lo.u;
}

// ===================== cp.async helpers =====================
__device__ __forceinline__ void cp_async16(uint32_t dst, const void* src, bool pred) {
    int sz = pred ? 16 : 0;
    asm volatile("cp.async.cg.shared.global [%0], [%1], 16, %2;"
                 :: "r"(dst), "l"(src), "r"(sz) : "memory");
}
#define CP_COMMIT() asm volatile("cp.async.commit_group;" ::: "memory")
#define CP_WAIT(n)  asm volatile("cp.async.wait_group %0;" :: "n"(n) : "memory")

enum { EP_NONE = 0, EP_ADD = 1, EP_TANH = 2, EP_SWIGLU = 3 };

// ===================== GEMM A: BK=32 stages (BM128/BN128, NST=2) ===========
#define BN 128
#define PAD 40                          // 32 + 8 bf16; pitch 80B

__device__ __forceinline__ void load_hl128(uint32_t sbase,
                                           const __nv_bfloat16* __restrict__ A,
                                           const __nv_bfloat16* __restrict__ Bm,
                                           int m0, int n0, int N, int K,
                                           int kp, int tid) {
    const int ld2 = 2 * K;
#pragma unroll
    for (int part = 0; part < 2; part++) {
        const __nv_bfloat16* src = A + part * K + kp * 32;
#pragma unroll
        for (int it = 0; it < 2; it++) {
            int id = it * 256 + tid;
            int r = id >> 2, c = id & 3;
            uint32_t dst = sbase + (uint32_t)((part * 128 + r) * PAD + c * 8) * 2;
            cp_async16(dst, src + (size_t)(m0 + r) * ld2 + c * 8, true);
        }
    }
#pragma unroll
    for (int part = 0; part < 2; part++) {
        const __nv_bfloat16* src = Bm + part * K + kp * 32;
#pragma unroll
        for (int it = 0; it < 2; it++) {
            int id = it * 256 + tid;
            int r = id >> 2, c = id & 3;
            bool ok = (n0 + r) < N;
            int gn = ok ? (n0 + r) : 0;
            uint32_t dst = sbase +
                (uint32_t)((256 + part * BN + r) * PAD + c * 8) * 2;
            cp_async16(dst, src + (size_t)gn * ld2 + c * 8, ok);
        }
    }
}

template <int EPI>
__global__ __launch_bounds__(256, 2)
void gemm_hl(const __nv_bfloat16* __restrict__ A,
             const __nv_bfloat16* __restrict__ Bm,
             float* __restrict__ C,
             int M, int N, int K) {
    constexpr int NJ      = 4;                  // BM128: 4 warps M, 2 warps N
    constexpr int STAGE_E = (2 * 128 + 2 * BN) * PAD;
    constexpr int STAGE_B = STAGE_E * 2;

    extern __shared__ __nv_bfloat16 smem[];
    const uint32_t sm0 = (uint32_t)__cvta_generic_to_shared(smem);
    const int tid  = threadIdx.x;
    const int warp = tid >> 5, lane = tid & 31;
    const int wm = warp % 4;
    const int wn = warp / 4;
    const int m0 = blockIdx.x * 128;
    const int n0 = blockIdx.y * BN;
    const int NK = K / 32;

    wmma::fragment<wmma::accumulator, 16, 16, 16, float> acc[2][NJ];
#pragma unroll
    for (int i = 0; i < 2; i++)
#pragma unroll
        for (int j = 0; j < NJ; j++) wmma::fill_fragment(acc[i][j], 0.f);

    load_hl128(sm0, A, Bm, m0, n0, N, K, 0, tid);
    CP_COMMIT();

    for (int kt = 0; kt < NK; kt++) {
        CP_WAIT(0);
        __syncthreads();
        int cn = kt + 1;
        if (cn < NK) {
            load_hl128(sm0 + (cn & 1) * STAGE_B, A, Bm, m0, n0, N, K, cn, tid);
            CP_COMMIT();
        }

        const __nv_bfloat16* st = smem + (size_t)(kt & 1) * STAGE_E;
        const __nv_bfloat16* aH = st;
        const __nv_bfloat16* aL = st + 128 * PAD;
        const __nv_bfloat16* bH = st + 256 * PAD;
        const __nv_bfloat16* bL = bH + BN * PAD;
#pragma unroll
        for (int ks = 0; ks < 2; ks++) {
            wmma::fragment<wmma::matrix_a, 16, 16, 16, __nv_bfloat16, wmma::row_major> afH[2], afL[2];
            wmma::fragment<wmma::matrix_b, 16, 16, 16, __nv_bfloat16, wmma::col_major> bfH[NJ], bfL[NJ];
#pragma unroll
            for (int i = 0; i < 2; i++) {
                wmma::load_matrix_sync(afH[i], aH + (wm * 32 + i * 16) * PAD + ks * 16, PAD);
                wmma::load_matrix_sync(afL[i], aL + (wm * 32 + i * 16) * PAD + ks * 16, PAD);
            }
#pragma unroll
            for (int j = 0; j < NJ; j++) {
                wmma::load_matrix_sync(bfH[j], bH + (wn * (16 * NJ) + j * 16) * PAD + ks * 16, PAD);
                wmma::load_matrix_sync(bfL[j], bL + (wn * (16 * NJ) + j * 16) * PAD + ks * 16, PAD);
            }
#pragma unroll
            for (int i = 0; i < 2; i++)
#pragma unroll
                for (int j = 0; j < NJ; j++)
                    wmma::mma_sync(acc[i][j], afH[i], bfH[j], acc[i][j]);
#pragma unroll
            for (int i = 0; i < 2; i++)
#pragma unroll
                for (int j = 0; j < NJ; j++)
                    wmma::mma_sync(acc[i][j], afH[i], bfL[j], acc[i][j]);
#pragma unroll
            for (int i = 0; i < 2; i++)
#pragma unroll
                for (int j = 0; j < NJ; j++)
                    wmma::mma_sync(acc[i][j], afL[i], bfH[j], acc[i][j]);
        }
    }

    __syncthreads();
    float* scr = reinterpret_cast<float*>(smem) + warp * 256;
    __nv_bfloat16* Cb = reinterpret_cast<__nv_bfloat16*>(C);
#pragma unroll
    for (int i = 0; i < 2; i++) {
#pragma unroll
        for (int j = 0; j < NJ; j++) {
            wmma::store_matrix_sync(scr, acc[i][j], 16, wmma::mem_row_major);
            __syncwarp();
            int r0 = m0 + wm * 32 + i * 16;
            int c0 = n0 + wn * (16 * NJ) + j * 16;
            if (EPI == EP_TANH) {
#pragma unroll
                for (int e = lane; e < 256; e += 32) {
                    int rr = e >> 4, cc = e & 15;
                    int gc = c0 + cc;
                    if (gc < N) {
                        size_t off = (size_t)(r0 + rr) * N + gc;
                        C[off] = 30.f * tanhf(scr[e] * (1.f / 30.f));
                    }
                }
            } else {  // EP_SWIGLU
                int f0 = c0 >> 1;
#pragma unroll
                for (int e = lane; e < 128; e += 32) {
                    int rr = e >> 3, pp = e & 7;
                    float g = scr[rr * 16 + 2 * pp];
                    float u = scr[rr * 16 + 2 * pp + 1];
                    float v = (g / (1.f + expf(-g))) * u;
                    __nv_bfloat16 hh = __float2bfloat16(v);
                    __nv_bfloat16 ll = __float2bfloat16(v - __bfloat162float(hh));
                    size_t base = (size_t)(r0 + rr) * N;
                    Cb[base + f0 + pp]            = hh;
                    Cb[base + (N >> 1) + f0 + pp] = ll;
                }
            }
            __syncwarp();
        }
    }
}

// ===================== GEMM B: BK=64 stages (BM64/BN128, NST=2) ============
#define PAD2 72                          // 64 + 8 bf16; pitch 144B

__device__ __forceinline__ void load_hl64(uint32_t sbase,
                                          const __nv_bfloat16* __restrict__ A,
                                          const __nv_bfloat16* __restrict__ Bm,
                                          int m0, int n0, int K, int kp, int tid) {
    const int ld2 = 2 * K;
#pragma unroll
    for (int part = 0; part < 2; part++) {          // A: hi, lo (64 rows x 8 chunks)
        const __nv_bfloat16* src = A + part * K + kp * 64;
#pragma unroll
        for (int it = 0; it < 2; it++) {
            int id = it * 256 + tid;
            int r = id >> 3, c = id & 7;
            uint32_t dst = sbase + (uint32_t)((part * 64 + r) * PAD2 + c * 8) * 2;
            cp_async16(dst, src + (size_t)(m0 + r) * ld2 + c * 8, true);
        }
    }
#pragma unroll
    for (int part = 0; part < 2; part++) {          // B: hi, lo (128 rows x 8 chunks)
        const __nv_bfloat16* src = Bm + part * K + kp * 64;
#pragma unroll
        for (int it = 0; it < 4; it++) {
            int id = it * 256 + tid;
            int r = id >> 3, c = id & 7;
            uint32_t dst = sbase +
                (uint32_t)((128 + part * 128 + r) * PAD2 + c * 8) * 2;
            cp_async16(dst, src + (size_t)(n0 + r) * ld2 + c * 8, true);
        }
    }
}

template <int EPI>
__global__ __launch_bounds__(256, 2)
void gemm_hl64(const __nv_bfloat16* __restrict__ A,
               const __nv_bfloat16* __restrict__ Bm,
               float* __restrict__ C,
               int M, int N, int K) {
    constexpr int NJ      = 2;                  // BM64: 2 warps M, 4 warps N
    constexpr int STAGE_E = (2 * 64 + 2 * 128) * PAD2;   // 384*72
    constexpr int STAGE_B = STAGE_E * 2;                 // 55296 B

    extern __shared__ __nv_bfloat16 smem[];
    const uint32_t sm0 = (uint32_t)__cvta_generic_to_shared(smem);
    const int tid  = threadIdx.x;
    const int warp = tid >> 5;
    const int wm = warp % 2;
    const int wn = warp / 2;
    const int m0 = blockIdx.x * 64;
    const int n0 = blockIdx.y * 128;
    const int NK = K / 64;

    wmma::fragment<wmma::accumulator, 16, 16, 16, float> acc[2][NJ];
#pragma unroll
    for (int i = 0; i < 2; i++)
#pragma unroll
        for (int j = 0; j < NJ; j++) wmma::fill_fragment(acc[i][j], 0.f);

    load_hl64(sm0, A, Bm, m0, n0, K, 0, tid);
    CP_COMMIT();

    for (int kt = 0; kt < NK; kt++) {
        CP_WAIT(0);
        __syncthreads();
        int cn = kt + 1;
        if (cn < NK) {
            load_hl64(sm0 + (cn & 1) * STAGE_B, A, Bm, m0, n0, K, cn, tid);
            CP_COMMIT();
        }

        const __nv_bfloat16* st = smem + (size_t)(kt & 1) * STAGE_E;
        const __nv_bfloat16* aH = st;
        const __nv_bfloat16* aL = st + 64 * PAD2;
        const __nv_bfloat16* bH = st + 128 * PAD2;
        const __nv_bfloat16* bL = bH + 128 * PAD2;
#pragma unroll
        for (int ks = 0; ks < 4; ks++) {
            wmma::fragment<wmma::matrix_a, 16, 16, 16, __nv_bfloat16, wmma::row_major> afH[2], afL[2];
            wmma::fragment<wmma::matrix_b, 16, 16, 16, __nv_bfloat16, wmma::col_major> bfH[NJ], bfL[NJ];
#pragma unroll
            for (int i = 0; i < 2; i++) {
                wmma::load_matrix_sync(afH[i], aH + (wm * 32 + i * 16) * PAD2 + ks * 16, PAD2);
                wmma::load_matrix_sync(afL[i], aL + (wm * 32 + i * 16) * PAD2 + ks * 16, PAD2);
            }
#pragma unroll
            for (int j = 0; j < NJ; j++) {
                wmma::load_matrix_sync(bfH[j], bH + (wn * 32 + j * 16) * PAD2 + ks * 16, PAD2);
                wmma::load_matrix_sync(bfL[j], bL + (wn * 32 + j * 16) * PAD2 + ks * 16, PAD2);
            }
#pragma unroll
            for (int i = 0; i < 2; i++)
#pragma unroll
                for (int j = 0; j < NJ; j++)
                    wmma::mma_sync(acc[i][j], afH[i], bfH[j], acc[i][j]);
#pragma unroll
            for (int i = 0; i < 2; i++)
#pragma unroll
                for (int j = 0; j < NJ; j++)
                    wmma::mma_sync(acc[i][j], afH[i], bfL[j], acc[i][j]);
#pragma unroll
            for (int i = 0; i < 2; i++)
#pragma unroll
                for (int j = 0; j < NJ; j++)
                    wmma::mma_sync(acc[i][j], afL[i], bfH[j], acc[i][j]);
        }
    }

    // direct fragment epilogue (N % 128 == 0 at all call sites)
#pragma unroll
    for (int i = 0; i < 2; i++) {
#pragma unroll
        for (int j = 0; j < NJ; j++) {
            int r0 = m0 + wm * 32 + i * 16;
            int c0 = n0 + wn * 32 + j * 16;
            float* cp = C + (size_t)r0 * N + c0;
            if (EPI == EP_ADD) {
                wmma::fragment<wmma::accumulator, 16, 16, 16, float> cf;
                wmma::load_matrix_sync(cf, cp, N, wmma::mem_row_major);
#pragma unroll
                for (int e = 0; e < cf.num_elements; e++)
                    acc[i][j].x[e] += cf.x[e];
            }
            wmma::store_matrix_sync(cp, acc[i][j], N, wmma::mem_row_major);
        }
    }
}

// ===================== elementwise kernels =====================
__global__ void embed_kernel(const int* __restrict__ idx, const float* __restrict__ tok) {
    int i = blockIdx.x * 256 + threadIdx.x;
    int bt = i >> 10;
    int e  = i & (E_ - 1);
    float v = tok[(size_t)idx[bt] * E_ + e];
    g_x[i]  = v;
    g_x0[i] = v;
}

__global__ void rope_table_kernel() {
    int i = blockIdx.x * 256 + threadIdx.x;
    int t = i >> 6, d = i & 63;
    float ang = (float)t * powf(10000.f, -(float)(d & 31) * (1.f / 32.f));
    float s, c;
    sincosf(ang, &s, &c);
    g_cosT[i] = c;
    g_sinT[i] = s;
}

// rmsnorm -> split bf16 activation; optional fused ve-gate (needs h[0:32])
__global__ void rmsnorm_split(const float* __restrict__ x, const float* __restrict__ w,
                              __nv_bfloat16* __restrict__ a2,
                              const float* __restrict__ vgw) {
    __shared__ float red[8];
    __shared__ float h32[32];
    int row = blockIdx.x;
    int tid = threadIdx.x;
    const float4 xv = ((const float4*)(x + (size_t)row * E_))[tid];
    float s = xv.x*xv.x + xv.y*xv.y + xv.z*xv.z + xv.w*xv.w;
#pragma unroll
    for (int o = 16; o; o >>= 1) s += __shfl_xor_sync(0xFFFFFFFFu, s, o);
    if ((tid & 31) == 0) red[tid >> 5] = s;
    __syncthreads();
    if (tid == 0) {
        float t = 0.f;
#pragma unroll
        for (int i = 0; i < 8; i++) t += red[i];
        red[0] = rsqrtf(t * (1.f / E_) + 1e-6f);
    }
    __syncthreads();
    float norm = red[0];
    const float4 wv = ((const float4*)w)[tid];
    float v[4] = {xv.x*norm*wv.x, xv.y*norm*wv.y, xv.z*norm*wv.z, xv.w*norm*wv.w};
    if (vgw && tid < 8) {
        h32[tid * 4]     = v[0];
        h32[tid * 4 + 1] = v[1];
        h32[tid * 4 + 2] = v[2];
        h32[tid * 4 + 3] = v[3];
    }
    union { __nv_bfloat162 b2[2]; uint2 u; } hi, lo;
#pragma unroll
    for (int j = 0; j < 2; j++) {
        __nv_bfloat16 h0 = __float2bfloat16(v[2*j]);
        __nv_bfloat16 h1 = __float2bfloat16(v[2*j+1]);
        hi.b2[j] = __nv_bfloat162(h0, h1);
        lo.b2[j] = __floats2bfloat162_rn(v[2*j] - __bfloat162float(h0),
                                         v[2*j+1] - __bfloat162float(h1));
    }
    __nv_bfloat16* dbase = a2 + (size_t)row * 2 * E_ + tid * 4;
    *((uint2*)dbase)        = hi.u;
    *((uint2*)(dbase + E_)) = lo.u;
    if (vgw) {
        __syncthreads();
        if (tid < H_) {
            const float* wr = vgw + tid * 32;
            float g = 0.f;
#pragma unroll
            for (int c = 0; c < 32; c++) g = fmaf(h32[c], wr[c], g);
            g_gate[row * H_ + tid] = 2.f / (1.f + expf(-g));
        }
    }
}

// rope + head split + gate; writes split bf16 q/k/v [bh][t][hi|lo]
__global__ void rope_split_kernel(const float* __restrict__ qkv, int has_gate) {
    int bt = blockIdx.x;
    int b = bt / T_, t = bt % T_;
    const float* src = qkv + (size_t)bt * 3 * E_;
    const float* ct = g_cosT + t * HD_;
    const float* st = g_sinT + t * HD_;
#pragma unroll
    for (int which = 0; which < 2; ++which) {
        const float* sp = src + which * E_;
        __nv_bfloat16* dst = (which == 0) ? g_q2 : g_k2;
        for (int item = threadIdx.x; item < H_ * 32; item += blockDim.x) {
            int h = item >> 5, p = item & 31;
            int d0 = 2 * p, d1 = 2 * p + 1;
            float c0 = ct[d0], s0 = st[d0];
            float c1 = ct[d1], s1 = st[d1];
            float x0v = sp[h * HD_ + d0];
            float x1v = sp[h * HD_ + d1];
            float o0 = x0v * c0 - x1v * s0;
            float o1 = x1v * c1 + x0v * s1;
            __nv_bfloat16* row = dst + ((size_t)(b * H_ + h) * T_ + t) * 128;
            split_store(row, d0, o0);
            split_store(row, d1, o1);
        }
    }
    for (int item = threadIdx.x; item < E_; item += blockDim.x) {
        int h = item >> 6, d = item & 63;
        float vv = src[2 * E_ + item];
        if (has_gate)
            vv += g_gate[bt * H_ + h] * g_x0[(size_t)bt * E_ + item];
        __nv_bfloat16* row = g_v2 + ((size_t)(b * H_ + h) * T_ + t) * 128;
        split_store(row, d, vv);
    }
}

// ===================== tensor-core causal attention =====================
#define ATP 72      // bf16 pitch
#define ATF 68      // fp32 pitch
#define AT_SMEM (8 * 64 * ATP * 2 + 2 * 64 * ATF * 4 + 3 * 64 * 4)   // 109312

__device__ __forceinline__ void at_load_tile(uint32_t dstH, uint32_t dstL,
                                             const __nv_bfloat16* src, int tid) {
#pragma unroll
    for (int it = 0; it < 4; it++) {
        int id = it * 128 + tid;
        int r = id >> 3, c = id & 7;
        cp_async16(dstH + (uint32_t)(r * ATP + c * 8) * 2, src + r * 128 + c * 8, true);
        cp_async16(dstL + (uint32_t)(r * ATP + c * 8) * 2, src + r * 128 + 64 + c * 8, true);
    }
}

__global__ __launch_bounds__(128, 2) void attn_tc() {
    extern __shared__ char smc[];
    __nv_bfloat16* QH = (__nv_bfloat16*)smc;
    __nv_bfloat16* QL = QH + 64 * ATP;
    __nv_bfloat16* KH = QL + 64 * ATP;
    __nv_bfloat16* KL = KH + 64 * ATP;
    __nv_bfloat16* VH = KL + 64 * ATP;
    __nv_bfloat16* VL = VH + 64 * ATP;
    __nv_bfloat16* PH = VL + 64 * ATP;
    __nv_bfloat16* PL = PH + 64 * ATP;
    float* S  = (float*)(PL + 64 * ATP);
    float* O  = S + 64 * ATF;
    float* Ms = O + 64 * ATF;
    float* Lv = Ms + 64;
    float* CR = Lv + 64;

    const int tid  = threadIdx.x;
    const int warp = tid >> 5;
    const int bh = blockIdx.y;
    const int qt = gridDim.x - 1 - blockIdx.x;

    const uint32_t qh_a = (uint32_t)__cvta_generic_to_shared(QH);
    const uint32_t ql_a = (uint32_t)__cvta_generic_to_shared(QL);
    const uint32_t kh_a = (uint32_t)__cvta_generic_to_shared(KH);
    const uint32_t kl_a = (uint32_t)__cvta_generic_to_shared(KL);
    const uint32_t vh_a = (uint32_t)__cvta_generic_to_shared(VH);
    const uint32_t vl_a = (uint32_t)__cvta_generic_to_shared(VL);

    const __nv_bfloat16* kbase = g_k2 + (size_t)bh * T_ * 128;
    const __nv_bfloat16* vbase = g_v2 + (size_t)bh * T_ * 128;

    at_load_tile(qh_a, ql_a, g_q2 + ((size_t)bh * T_ + qt * 64) * 128, tid);
    // prologue: K(0), V(0)
    at_load_tile(kh_a, kl_a, kbase, tid);
    at_load_tile(vh_a, vl_a, vbase, tid);
    CP_COMMIT();

    for (int e = tid; e < 4096; e += 128)
        O[(e >> 6) * ATF + (e & 63)] = 0.f;
    if (tid < 64) { Ms[tid] = -1e30f; Lv[tid] = 0.f; }

    for (int kt = 0; kt <= qt; kt++) {
        CP_WAIT(0);
        __syncthreads();

        // S = Q K^T  (consumes KH/KL)
        {
            wmma::fragment<wmma::accumulator, 16, 16, 16, float> sacc[4];
#pragma unroll
            for (int j = 0; j < 4; j++) wmma::fill_fragment(sacc[j], 0.f);
#pragma unroll
            for (int ks = 0; ks < 4; ks++) {
                wmma::fragment<wmma::matrix_a, 16, 16, 16, __nv_bfloat16, wmma::row_major> aH, aL;
                wmma::fragment<wmma::matrix_b, 16, 16, 16, __nv_bfloat16, wmma::col_major> bH[4], bL[4];
                wmma::load_matrix_sync(aH, QH + (warp * 16) * ATP + ks * 16, ATP);
                wmma::load_matrix_sync(aL, QL + (warp * 16) * ATP + ks * 16, ATP);
#pragma unroll
                for (int j = 0; j < 4; j++) {
                    wmma::load_matrix_sync(bH[j], KH + (j * 16) * ATP + ks * 16, ATP);
                    wmma::load_matrix_sync(bL[j], KL + (j * 16) * ATP + ks * 16, ATP);
                }
#pragma unroll
                for (int j = 0; j < 4; j++) wmma::mma_sync(sacc[j], aH, bH[j], sacc[j]);
#pragma unroll
                for (int j = 0; j < 4; j++) wmma::mma_sync(sacc[j], aH, bL[j], sacc[j]);
#pragma unroll
                for (int j = 0; j < 4; j++) wmma::mma_sync(sacc[j], aL, bH[j], sacc[j]);
            }
#pragma unroll
            for (int j = 0; j < 4; j++)
                wmma::store_matrix_sync(S + (warp * 16) * ATF + j * 16, sacc[j], ATF,
                                        wmma::mem_row_major);
        }
        __syncthreads();

        // K buffer now dead: prefetch K(kt+1) overlapped with softmax+PV
        if (kt < qt) {
            at_load_tile(kh_a, kl_a, kbase + (size_t)(kt + 1) * 64 * 128, tid);
            CP_COMMIT();
        }

        // online softmax (2 threads per row)
        {
            int r = tid >> 1, hf = tid & 1;
            int q = qt * 64 + r;
            int jmax = q - kt * 64 + 1;
            if (jmax > 64) jmax = 64;
            const float* srow = S + r * ATF + hf * 32;
            int base = hf * 32;
            float mo = Ms[r], mx = mo;
#pragma unroll
            for (int j = 0; j < 32; j++) {
                if (base + j < jmax) mx = fmaxf(mx, srow[j] * 0.125f);
            }
            mx = fmaxf(mx, __shfl_xor_sync(0xFFFFFFFFu, mx, 1));
            float corr = __expf(mo - mx);
            float lsum = 0.f;
#pragma unroll
            for (int j = 0; j < 32; j++) {
                int gj = base + j;
                float p = (gj < jmax) ? __expf(srow[j] * 0.125f - mx) : 0.f;
                lsum += p;
                __nv_bfloat16 ph = __float2bfloat16(p);
                PH[r * ATP + gj] = ph;
                PL[r * ATP + gj] = __float2bfloat16(p - __bfloat162float(ph));
            }
            lsum += __shfl_xor_sync(0xFFFFFFFFu, lsum, 1);
            if (hf == 0) {
                Lv[r] = Lv[r] * corr + lsum;
                Ms[r] = mx;
                CR[r] = corr;
            }
        }
        __syncthreads();

        // PV into S temp (consumes VH/VL)
        {
            wmma::fragment<wmma::accumulator, 16, 16, 16, float> oacc[4];
#pragma unroll
            for (int j = 0; j < 4; j++) wmma::fill_fragment(oacc[j], 0.f);
#pragma unroll
            for (int ks = 0; ks < 4; ks++) {
                wmma::fragment<wmma::matrix_a, 16, 16, 16, __nv_bfloat16, wmma::row_major> aH, aL;
                wmma::fragment<wmma::matrix_b, 16, 16, 16, __nv_bfloat16, wmma::row_major> bH[4], bL[4];
                wmma::load_matrix_sync(aH, PH + (warp * 16) * ATP + ks * 16, ATP);
                wmma::load_matrix_sync(aL, PL + (warp * 16) * ATP + ks * 16, ATP);
#pragma unroll
                for (int j = 0; j < 4; j++) {
                    wmma::load_matrix_sync(bH[j], VH + (ks * 16) * ATP + j * 16, ATP);
                    wmma::load_matrix_sync(bL[j], VL + (ks * 16) * ATP + j * 16, ATP);
                }
#pragma unroll
                for (int j = 0; j < 4; j++) wmma::mma_sync(oacc[j], aH, bH[j], oacc[j]);
#pragma unroll
                for (int j = 0; j < 4; j++) wmma::mma_sync(oacc[j], aH, bL[j], oacc[j]);
#pragma unroll
                for (int j = 0; j < 4; j++) wmma::mma_sync(oacc[j], aL, bH[j], oacc[j]);
            }
            __syncthreads();   // softmax S reads done + V fragment reads done
#pragma unroll
            for (int j = 0; j < 4; j++)
                wmma::store_matrix_sync(S + (warp * 16) * ATF + j * 16, oacc[j], ATF,
                                        wmma::mem_row_major);
        }

        // V buffer now dead: prefetch V(kt+1) overlapped with O update
        if (kt < qt) {
            at_load_tile(vh_a, vl_a, vbase + (size_t)(kt + 1) * 64 * 128, tid);
            CP_COMMIT();
        }
        __syncthreads();

        // O = O*corr + PV
        for (int e = tid; e < 4096; e += 128) {
            int r = e >> 6, c = e & 63;
            O[r * ATF + c] = O[r * ATF + c] * CR[r] + S[r * ATF + c];
        }
        __syncthreads();
    }

    if (tid < 64) CR[tid] = 1.f / Lv[tid];
    __syncthreads();
    int b = bh / H_, h = bh % H_;
    for (int e = tid; e < 4096; e += 128) {
        int r = e >> 6, c = e & 63;
        int q = qt * 64 + r;
        float v = O[r * ATF + c] * CR[r];
        __nv_bfloat16 hh = __float2bfloat16(v);
        __nv_bfloat16 ll = __float2bfloat16(v - __bfloat162float(hh));
        size_t base = (size_t)(b * T_ + q) * 2 * E_ + h * 64 + c;
        g_a2s[base]      = hh;
        g_a2s[base + E_] = ll;
    }
}

// ===================== host-side launchers =====================
template <int EPI>
static void run_gemm128(const __nv_bfloat16* A2, const __nv_bfloat16* B2, float* C,
                        int M, int N, int K) {
    constexpr size_t SMB = 2 * (size_t)(2 * 128 + 2 * BN) * PAD * 2;  // 81920
    dim3 grid(M / 128, (N + BN - 1) / BN);
    gemm_hl<EPI><<<grid, 256, SMB>>>(A2, B2, C, M, N, K);
}

template <int EPI>
static void run_gemm64(const __nv_bfloat16* A2, const __nv_bfloat16* B2, float* C,
                       int M, int N, int K) {
    constexpr size_t SMB = 2 * (size_t)(2 * 64 + 2 * 128) * PAD2 * 2; // 110592
    dim3 grid(M / 64, N / 128);
    gemm_hl64<EPI><<<grid, 256, SMB>>>(A2, B2, C, M, N, K);
}

static void run_cvt2(const float* src, __nv_bfloat16* dst, int K, long long rows,
                     int RPL, long long ostride, int ooff, int rmul = 1) {
    long long total8 = rows * K / 8;
    unsigned blocks = (unsigned)((total8 + 255) / 256);
    cvt2<<<blocks, 256>>>(src, dst, K, total8, RPL, ostride, ooff, rmul);
}

// ===================== launch =====================
extern "C" void kernel_launch(void* const* d_in, const int* in_sizes, int n_in,
                              void* d_out, int out_size) {
    const int*   idx  = (const int*)  d_in[0];
    const float* tok  = (const float*)d_in[1];
    const float* ln1  = (const float*)d_in[2];
    const float* qkvw = (const float*)d_in[3];
    const float* outw = (const float*)d_in[4];
    const float* vgw  = (const float*)d_in[5];
    const float* ln2  = (const float*)d_in[6];
    const float* wgw  = (const float*)d_in[7];
    const float* wuw  = (const float*)d_in[8];
    const float* wdw  = (const float*)d_in[9];
    const float* lnf  = (const float*)d_in[10];
    float* out = (float*)d_out;

    constexpr int SMB128 = 2 * (2 * 128 + 2 * BN) * PAD * 2;   // 81920
    constexpr int SMB64  = 2 * (2 * 64 + 2 * 128) * PAD2 * 2;  // 110592
    cudaFuncSetAttribute((void*)gemm_hl64<EP_NONE>,
                         cudaFuncAttributeMaxDynamicSharedMemorySize, SMB64);
    cudaFuncSetAttribute((void*)gemm_hl64<EP_ADD>,
                         cudaFuncAttributeMaxDynamicSharedMemorySize, SMB64);
    cudaFuncSetAttribute((void*)gemm_hl<EP_SWIGLU>,
                         cudaFuncAttributeMaxDynamicSharedMemorySize, SMB128);
    cudaFuncSetAttribute((void*)gemm_hl<EP_TANH>,
                         cudaFuncAttributeMaxDynamicSharedMemorySize, SMB128);
    cudaFuncSetAttribute((void*)attn_tc,
                         cudaFuncAttributeMaxDynamicSharedMemorySize, AT_SMEM);

    float *x, *qkv;
    cudaGetSymbolAddress((void**)&x,   g_x);
    cudaGetSymbolAddress((void**)&qkv, g_qkv);

    __nv_bfloat16 *wqkv2, *wout2, *wgu2, *wd2, *tok2, *a2s, *a2b;
    cudaGetSymbolAddress((void**)&wqkv2, g_wqkv2);
    cudaGetSymbolAddress((void**)&wout2, g_wout2);
    cudaGetSymbolAddress((void**)&wgu2,  g_wgu2);
    cudaGetSymbolAddress((void**)&wd2,   g_wd2);
    cudaGetSymbolAddress((void**)&tok2,  g_tok2);
    cudaGetSymbolAddress((void**)&a2s,   g_a2s);
    cudaGetSymbolAddress((void**)&a2b,   g_a2b);

    // ---- one-time prep ----
    rope_table_kernel<<<(T_ * HD_) / 256, 256>>>();
    run_cvt2(qkvw, wqkv2, E_,  (long long)L_ * 3 * E_, 3 * E_,  3 * E_,  0);
    run_cvt2(outw, wout2, E_,  (long long)L_ * E_,     E_,      E_,      0);
    run_cvt2(wgw,  wgu2,  E_,  (long long)L_ * FF_,    FF_,     2 * FF_, 0, 2);
    run_cvt2(wuw,  wgu2,  E_,  (long long)L_ * FF_,    FF_,     2 * FF_, 1, 2);
    run_cvt2(wdw,  wd2,   FF_, (long long)L_ * E_,     E_,      E_,      0);
    run_cvt2(tok,  tok2,  E_,  (long long)V_,          V_,      V_,      0);

    embed_kernel<<<(M_ * E_) / 256, 256>>>(idx, tok);

    for (int i = 0; i < L_; i++) {
        rmsnorm_split<<<M_, 256>>>(x, ln1 + i * E_, a2s,
                                   (i & 1) ? (vgw + (size_t)i * H_ * 32) : nullptr);
        run_gemm64<EP_NONE>(a2s, wqkv2 + (size_t)i * 3 * E_ * 2 * E_,
                            qkv, M_, 3 * E_, E_);
        rope_split_kernel<<<M_, 256>>>(qkv, i & 1);
        attn_tc<<<dim3(T_ / 64, B_ * H_), 128, AT_SMEM>>>();   // writes split into a2s
        run_gemm64<EP_ADD>(a2s, wout2 + (size_t)i * E_ * 2 * E_, x, M_, E_, E_);

        rmsnorm_split<<<M_, 256>>>(x, ln2 + i * E_, a2s, nullptr);
        run_gemm128<EP_SWIGLU>(a2s, wgu2 + (size_t)i * 2 * FF_ * 2 * E_,
                               (float*)a2b, M_, 2 * FF_, E_);
        run_gemm64<EP_ADD>(a2b, wd2 + (size_t)i * E_ * 2 * FF_, x, M_, E_, FF_);
    }

    rmsnorm_split<<<M_, 256>>>(x, lnf, a2s, nullptr);
    run_gemm128<EP_TANH>(a2s, tok2, out, M_, V_, E_);
}